// round 1
// baseline (speedup 1.0000x reference)
#include <cuda_runtime.h>
#include <cstdint>

#define BN_T 2048
#define DM   1024
#define NH   16
#define HD   64
#define MROWS 8192   // B*T

// Scratch (device globals: allocation-free per harness rules)
__device__ float g_qkv[MROWS * 3 * DM];  // [8192, 3072]
__device__ float g_y[MROWS * DM];        // [8192, 1024]

// ---------------------------------------------------------------------------
// C[M,N] = A[M,K] @ B[N,K]^T + bias[N]
// 128x128 tile, BK=8, 256 threads, 8x8 per thread. M,N,K multiples of 128/8.
// ---------------------------------------------------------------------------
__global__ __launch_bounds__(256) void sgemm_tn_bias(
    const float* __restrict__ A,
    const float* __restrict__ Bw,
    const float* __restrict__ bias,
    float* __restrict__ C,
    int M, int N, int K)
{
    __shared__ float As[8][128];
    __shared__ float Bs[8][128];

    const int tid = threadIdx.x;
    const int bm = blockIdx.y * 128;
    const int bn = blockIdx.x * 128;

    const int loadRow = tid >> 1;          // 0..127
    const int loadCol = (tid & 1) * 4;     // 0 or 4

    const float* Aptr = A + (size_t)(bm + loadRow) * K + loadCol;
    const float* Bptr = Bw + (size_t)(bn + loadRow) * K + loadCol;

    const int tx = tid & 15;
    const int ty = tid >> 4;

    float acc[8][8];
#pragma unroll
    for (int i = 0; i < 8; i++)
#pragma unroll
        for (int j = 0; j < 8; j++) acc[i][j] = 0.f;

    for (int k0 = 0; k0 < K; k0 += 8) {
        float4 a4 = *(const float4*)(Aptr + k0);
        float4 b4 = *(const float4*)(Bptr + k0);
        __syncthreads();
        As[loadCol + 0][loadRow] = a4.x;
        As[loadCol + 1][loadRow] = a4.y;
        As[loadCol + 2][loadRow] = a4.z;
        As[loadCol + 3][loadRow] = a4.w;
        Bs[loadCol + 0][loadRow] = b4.x;
        Bs[loadCol + 1][loadRow] = b4.y;
        Bs[loadCol + 2][loadRow] = b4.z;
        Bs[loadCol + 3][loadRow] = b4.w;
        __syncthreads();

#pragma unroll
        for (int kk = 0; kk < 8; kk++) {
            float ar[8], br[8];
            *(float4*)(ar)     = *(const float4*)&As[kk][ty * 4];
            *(float4*)(ar + 4) = *(const float4*)&As[kk][ty * 4 + 64];
            *(float4*)(br)     = *(const float4*)&Bs[kk][tx * 4];
            *(float4*)(br + 4) = *(const float4*)&Bs[kk][tx * 4 + 64];
#pragma unroll
            for (int i = 0; i < 8; i++)
#pragma unroll
                for (int j = 0; j < 8; j++)
                    acc[i][j] += ar[i] * br[j];
        }
    }

    // Epilogue: add bias, write with float4 stores
#pragma unroll
    for (int i = 0; i < 8; i++) {
        int row = bm + ((i < 4) ? (ty * 4 + i) : (64 + ty * 4 + i - 4));
        float* Crow = C + (size_t)row * N + bn;
#pragma unroll
        for (int jg = 0; jg < 2; jg++) {
            int cbase = tx * 4 + jg * 64;
            float4 v;
            v.x = acc[i][jg * 4 + 0] + bias[bn + cbase + 0];
            v.y = acc[i][jg * 4 + 1] + bias[bn + cbase + 1];
            v.z = acc[i][jg * 4 + 2] + bias[bn + cbase + 2];
            v.w = acc[i][jg * 4 + 3] + bias[bn + cbase + 3];
            *(float4*)(Crow + cbase) = v;
        }
    }
}

// ---------------------------------------------------------------------------
// Causal flash attention, fp32.
// qkv: [B*T, 3*DM], layout per row: [q(1024) | k(1024) | v(1024)], head h at h*64.
// Grid: (T/64, B*NH). Block: 128 threads; 2 threads per query (each 32 dims).
// Writes y[B*T, DM] with invalid query rows zeroed.
// ---------------------------------------------------------------------------
#define QT 64
#define KT 32

__global__ __launch_bounds__(128) void flash_fp32(
    const float* __restrict__ qkv,
    const int*   __restrict__ mask,
    float* __restrict__ y)
{
    const int qt = blockIdx.x;
    const int bh = blockIdx.y;
    const int b = bh >> 4;
    const int h = bh & 15;

    const int tid = threadIdx.x;
    const int ql = tid >> 1;        // 0..63
    const int half = tid & 1;       // 0 or 1
    const int qi = qt * QT + ql;    // global query index

    const float* base = qkv + (size_t)b * BN_T * 3072 + h * 64;

    // Load q row (my 32 dims), pre-scale by 1/sqrt(64)
    float qreg[32];
    {
        const float* qp = base + (size_t)qi * 3072 + half * 32;
#pragma unroll
        for (int i = 0; i < 32; i++) qreg[i] = qp[i] * 0.125f;
    }

    float o[32];
#pragma unroll
    for (int i = 0; i < 32; i++) o[i] = 0.f;
    float m = -1e30f, l = 0.f;

    __shared__ float ks[KT][64];
    __shared__ float vs[KT][64];

    const int nkt = qt * 2 + 2;     // key tiles covering [0, qt*64+63]

    for (int kt = 0; kt < nkt; kt++) {
        __syncthreads();
        {
            const int j = tid >> 2;         // 0..31
            const int f = tid & 3;          // 0..3
            const float* kp = base + (size_t)(kt * KT + j) * 3072 + 1024;
            const float* vp = kp + 1024;
#pragma unroll
            for (int it = 0; it < 4; it++) {
                int c = (f + it * 4) * 4;   // 0..60 step pattern covering 64
                *(float4*)&ks[j][c] = *(const float4*)(kp + c);
                *(float4*)&vs[j][c] = *(const float4*)(vp + c);
            }
        }
        __syncthreads();

        float s[KT];
#pragma unroll
        for (int j = 0; j < KT; j++) {
            float p = 0.f;
            const float* kr = &ks[j][half * 32];
#pragma unroll
            for (int i = 0; i < 32; i++) p += qreg[i] * kr[i];
            p += __shfl_xor_sync(0xffffffffu, p, 1);
            int kj = kt * KT + j;
            s[j] = (kj <= qi) ? p : -1e30f;
        }

        float mt = s[0];
#pragma unroll
        for (int j = 1; j < KT; j++) mt = fmaxf(mt, s[j]);
        float mnew = fmaxf(m, mt);
        float corr = __expf(m - mnew);

        float psum = 0.f;
#pragma unroll
        for (int j = 0; j < KT; j++) {
            float e = __expf(s[j] - mnew);
            s[j] = e;
            psum += e;
        }
        l = l * corr + psum;

#pragma unroll
        for (int d = 0; d < 32; d++) {
            float a = o[d] * corr;
#pragma unroll
            for (int j = 0; j < KT; j++)
                a += s[j] * vs[j][half * 32 + d];
            o[d] = a;
        }
        m = mnew;
    }

    const float inv = 1.f / l;
    const int valid = mask[b * BN_T + qi];
    const float qsc = valid ? inv : 0.f;

    float* yp = y + (size_t)(b * BN_T + qi) * DM + h * 64 + half * 32;
#pragma unroll
    for (int dg = 0; dg < 8; dg++) {
        float4 v;
        v.x = o[dg * 4 + 0] * qsc;
        v.y = o[dg * 4 + 1] * qsc;
        v.z = o[dg * 4 + 2] * qsc;
        v.w = o[dg * 4 + 3] * qsc;
        *(float4*)(yp + dg * 4) = v;
    }
}

// ---------------------------------------------------------------------------
extern "C" void kernel_launch(void* const* d_in, const int* in_sizes, int n_in,
                              void* d_out, int out_size)
{
    const float* x    = (const float*)d_in[0];
    const int*   mask = (const int*)  d_in[1];
    const float* Wqkv = (const float*)d_in[2];
    const float* bqkv = (const float*)d_in[3];
    const float* Wo   = (const float*)d_in[4];
    const float* bo   = (const float*)d_in[5];
    float* out = (float*)d_out;

    float *qkv, *yb;
    cudaGetSymbolAddress((void**)&qkv, g_qkv);
    cudaGetSymbolAddress((void**)&yb,  g_y);

    // QKV projection: [8192,3072] = x[8192,1024] @ Wqkv[3072,1024]^T + bqkv
    sgemm_tn_bias<<<dim3(3072 / 128, MROWS / 128), 256>>>(x, Wqkv, bqkv, qkv,
                                                          MROWS, 3 * DM, DM);

    // Causal flash attention -> y (invalid query rows zeroed)
    flash_fp32<<<dim3(BN_T / QT, 4 * NH), 128>>>(qkv, mask, yb);

    // Output projection: out = y @ Wo[1024,1024]^T + bo
    sgemm_tn_bias<<<dim3(DM / 128, MROWS / 128), 256>>>(yb, Wo, bo, out,
                                                        MROWS, DM, DM);
}

// round 3
// speedup vs baseline: 1.2599x; 1.2599x over previous
#include <cuda_runtime.h>
#include <cuda_bf16.h>
#include <cstdint>

#define BN_T 2048
#define DM   1024
#define NH   16
#define HD   64
#define MROWS 8192   // B*T

// ---------------------------------------------------------------------------
// Device-global scratch (allocation-free per harness rules)
// ---------------------------------------------------------------------------
__device__ __align__(16) float g_qkv[MROWS * 3 * DM];   // [8192, 3072] fp32
__device__ __align__(16) float g_y[MROWS * DM];         // [8192, 1024] fp32
__device__ __align__(16) __nv_bfloat16 g_xh[MROWS * DM];
__device__ __align__(16) __nv_bfloat16 g_xl[MROWS * DM];
__device__ __align__(16) __nv_bfloat16 g_wqkvh[3 * DM * DM];
__device__ __align__(16) __nv_bfloat16 g_wqkvl[3 * DM * DM];
__device__ __align__(16) __nv_bfloat16 g_woh[DM * DM];
__device__ __align__(16) __nv_bfloat16 g_wol[DM * DM];
__device__ __align__(16) __nv_bfloat16 g_yh[MROWS * DM];
__device__ __align__(16) __nv_bfloat16 g_yl[MROWS * DM];

// ---------------------------------------------------------------------------
// PTX helpers (baseline PTX only: cp.async + ldmatrix + mma.sync)
// ---------------------------------------------------------------------------
__device__ __forceinline__ uint32_t smem_u32(const void* p) {
    uint32_t a;
    asm("{ .reg .u64 t; cvta.to.shared.u64 t, %1; cvt.u32.u64 %0, t; }"
        : "=r"(a) : "l"(p));
    return a;
}

__device__ __forceinline__ void cp_async16(uint32_t saddr, const void* gaddr) {
    asm volatile("cp.async.cg.shared.global [%0], [%1], 16;"
                 :: "r"(saddr), "l"(gaddr) : "memory");
}
#define CP_COMMIT() asm volatile("cp.async.commit_group;" ::: "memory")
#define CP_WAIT(n)  asm volatile("cp.async.wait_group %0;" :: "n"(n) : "memory")

__device__ __forceinline__ void ldm4(uint32_t* r, uint32_t addr) {
    asm volatile("ldmatrix.sync.aligned.m8n8.x4.shared.b16 {%0,%1,%2,%3}, [%4];"
                 : "=r"(r[0]), "=r"(r[1]), "=r"(r[2]), "=r"(r[3]) : "r"(addr));
}

__device__ __forceinline__ void mma_bf16(float* d, const uint32_t* a,
                                         uint32_t b0, uint32_t b1) {
    asm volatile(
        "mma.sync.aligned.m16n8k16.row.col.f32.bf16.bf16.f32 "
        "{%0,%1,%2,%3}, {%4,%5,%6,%7}, {%8,%9}, {%0,%1,%2,%3};"
        : "+f"(d[0]), "+f"(d[1]), "+f"(d[2]), "+f"(d[3])
        : "r"(a[0]), "r"(a[1]), "r"(a[2]), "r"(a[3]), "r"(b0), "r"(b1));
}

// ---------------------------------------------------------------------------
// fp32 -> (hi, lo) bf16 split, 4 elems/thread
// ---------------------------------------------------------------------------
__global__ __launch_bounds__(256) void split_bf16(
    const float* __restrict__ in,
    __nv_bfloat16* __restrict__ hi,
    __nv_bfloat16* __restrict__ lo,
    int n4)
{
    int i = blockIdx.x * blockDim.x + threadIdx.x;
    if (i >= n4) return;
    float4 v = ((const float4*)in)[i];
    __nv_bfloat16 h0 = __float2bfloat16(v.x);
    __nv_bfloat16 h1 = __float2bfloat16(v.y);
    __nv_bfloat16 h2 = __float2bfloat16(v.z);
    __nv_bfloat16 h3 = __float2bfloat16(v.w);
    __nv_bfloat16 l0 = __float2bfloat16(v.x - __bfloat162float(h0));
    __nv_bfloat16 l1 = __float2bfloat16(v.y - __bfloat162float(h1));
    __nv_bfloat16 l2 = __float2bfloat16(v.z - __bfloat162float(h2));
    __nv_bfloat16 l3 = __float2bfloat16(v.w - __bfloat162float(h3));
    __nv_bfloat162 hp0(h0, h1), hp1(h2, h3), lp0(l0, l1), lp1(l2, l3);
    ((__nv_bfloat162*)hi)[i * 2]     = hp0;
    ((__nv_bfloat162*)hi)[i * 2 + 1] = hp1;
    ((__nv_bfloat162*)lo)[i * 2]     = lp0;
    ((__nv_bfloat162*)lo)[i * 2 + 1] = lp1;
}

// ---------------------------------------------------------------------------
// C[M,N] = A[M,K] @ B[N,K]^T + bias[N], split bf16 3-pass via mma.sync HMMA.
// CTA tile 128x128, BK=32, 3-stage cp.async pipeline, 256 threads,
// warp tile 32x64 (warp grid 4 in M x 2 in N).
// Requires K % 32 == 0, M % 128 == 0, N % 128 == 0.
// ---------------------------------------------------------------------------
#define STAGE_BYTES 32768             // Ah|Al|Bh|Bl, 8KB each (128 rows x 64B)
#define GEMM_SMEM  (3 * STAGE_BYTES)  // 96KB

// swizzled byte offset of chunk (row, c) within an 8KB sub-tile
__device__ __forceinline__ uint32_t sw_off(int row, int c) {
    return (uint32_t)(row * 64 + ((c ^ ((row >> 1) & 3)) * 16));
}

__global__ __launch_bounds__(256, 1) void gemm_bf16x3(
    const __nv_bfloat16* __restrict__ Ah, const __nv_bfloat16* __restrict__ Al,
    const __nv_bfloat16* __restrict__ Bh, const __nv_bfloat16* __restrict__ Bl,
    const float* __restrict__ bias,
    float* __restrict__ C,
    int N, int K)
{
    extern __shared__ char smem[];
    const uint32_t sb = smem_u32(smem);
    const int tid = threadIdx.x;
    const int lane = tid & 31;
    const int wid = tid >> 5;
    const int warpM = wid & 3;          // 0..3 -> mbase = warpM*32
    const int warpN = wid >> 2;         // 0..1 -> nbase = warpN*64
    const int bm = blockIdx.y * 128;
    const int bn = blockIdx.x * 128;
    const int NC = K >> 5;              // K chunks of 32

    // ldmatrix lane geometry
    const int g  = lane >> 3;
    const int l7 = lane & 7;
    const int arow = (g & 1) * 8 + l7;  // A: row within 16, chunk sel = g>>1
    const int acg  = g >> 1;
    const int brow = (g >> 1) * 8 + l7; // B: row within 16, chunk sel = g&1
    const int bcg  = g & 1;

    // Precompute ldmatrix row bases (byte offsets within an 8KB sub-tile)
    uint32_t aRow[2], aSw[2];
#pragma unroll
    for (int mt = 0; mt < 2; mt++) {
        int r = warpM * 32 + mt * 16 + arow;
        aRow[mt] = (uint32_t)(r * 64);
        aSw[mt] = (uint32_t)((r >> 1) & 3);
    }
    uint32_t bRow[4], bSw[4];
#pragma unroll
    for (int ng = 0; ng < 4; ng++) {
        int r = warpN * 64 + ng * 16 + brow;
        bRow[ng] = (uint32_t)(r * 64);
        bSw[ng] = (uint32_t)((r >> 1) & 3);
    }

    float acc[2][8][4];
#pragma unroll
    for (int mt = 0; mt < 2; mt++)
#pragma unroll
        for (int nt = 0; nt < 8; nt++)
#pragma unroll
            for (int e = 0; e < 4; e++) acc[mt][nt][e] = 0.f;

    // cp.async loader: chunk kc -> stage st
    const __nv_bfloat16* srcA[2] = { Ah + (size_t)bm * K, Al + (size_t)bm * K };
    const __nv_bfloat16* srcB[2] = { Bh + (size_t)bn * K, Bl + (size_t)bn * K };

    auto load_stage = [&](int kc, int st) {
        const uint32_t stbase = sb + st * STAGE_BYTES;
#pragma unroll
        for (int q = 0; q < 8; q++) {
            int cid = tid + q * 256;          // 0..2047
            int sub = cid >> 9;               // 0:Ah 1:Al 2:Bh 3:Bl
            int ci  = cid & 511;
            int row = ci >> 2;
            int c   = ci & 3;
            uint32_t saddr = stbase + sub * 8192 + sw_off(row, c);
            const __nv_bfloat16* gp =
                (sub < 2 ? srcA[sub] : srcB[sub - 2])
                + (size_t)row * K + kc * 32 + c * 8;
            cp_async16(saddr, gp);
        }
        CP_COMMIT();
    };

    load_stage(0, 0);
    load_stage(1, 1);

    for (int i = 0; i < NC; i++) {
        if (i < NC - 1) { CP_WAIT(1); } else { CP_WAIT(0); }
        __syncthreads();

        const uint32_t stbase = sb + (i % 3) * STAGE_BYTES;
#pragma unroll
        for (int ks = 0; ks < 2; ks++) {
            uint32_t ah[2][4], al[2][4];
#pragma unroll
            for (int mt = 0; mt < 2; mt++) {
                uint32_t slot = (uint32_t)((2 * ks + acg) ^ aSw[mt]) * 16;
                ldm4(ah[mt], stbase + 0    + aRow[mt] + slot);
                ldm4(al[mt], stbase + 8192 + aRow[mt] + slot);
            }
            uint32_t bh[4][4], bl[4][4];
#pragma unroll
            for (int ng = 0; ng < 4; ng++) {
                uint32_t slot = (uint32_t)((2 * ks + bcg) ^ bSw[ng]) * 16;
                ldm4(bh[ng], stbase + 16384 + bRow[ng] + slot);
                ldm4(bl[ng], stbase + 24576 + bRow[ng] + slot);
            }
#pragma unroll
            for (int mt = 0; mt < 2; mt++) {
#pragma unroll
                for (int ng = 0; ng < 4; ng++) {
                    // nt = 2*ng : b regs {0,1};  nt = 2*ng+1 : b regs {2,3}
                    mma_bf16(acc[mt][2 * ng],     ah[mt], bh[ng][0], bh[ng][1]);
                    mma_bf16(acc[mt][2 * ng],     ah[mt], bl[ng][0], bl[ng][1]);
                    mma_bf16(acc[mt][2 * ng],     al[mt], bh[ng][0], bh[ng][1]);
                    mma_bf16(acc[mt][2 * ng + 1], ah[mt], bh[ng][2], bh[ng][3]);
                    mma_bf16(acc[mt][2 * ng + 1], ah[mt], bl[ng][2], bl[ng][3]);
                    mma_bf16(acc[mt][2 * ng + 1], al[mt], bh[ng][2], bh[ng][3]);
                }
            }
        }

        __syncthreads();
        if (i + 2 < NC) load_stage(i + 2, (i + 2) % 3);
    }

    // Epilogue: bias + store fp32
#pragma unroll
    for (int mt = 0; mt < 2; mt++) {
#pragma unroll
        for (int nt = 0; nt < 8; nt++) {
            int row0 = bm + warpM * 32 + mt * 16 + (lane >> 2);
            int col  = bn + warpN * 64 + nt * 8 + (lane & 3) * 2;
            float b0 = bias[col], b1 = bias[col + 1];
            float2 v0 = { acc[mt][nt][0] + b0, acc[mt][nt][1] + b1 };
            float2 v1 = { acc[mt][nt][2] + b0, acc[mt][nt][3] + b1 };
            *(float2*)(C + (size_t)row0 * N + col) = v0;
            *(float2*)(C + (size_t)(row0 + 8) * N + col) = v1;
        }
    }
}

// ---------------------------------------------------------------------------
// Causal flash attention, fp32 (unchanged)
// ---------------------------------------------------------------------------
#define QT 64
#define KT 32

__global__ __launch_bounds__(128) void flash_fp32(
    const float* __restrict__ qkv,
    const int*   __restrict__ mask,
    float* __restrict__ y)
{
    const int qt = blockIdx.x;
    const int bh = blockIdx.y;
    const int b = bh >> 4;
    const int h = bh & 15;

    const int tid = threadIdx.x;
    const int ql = tid >> 1;
    const int half = tid & 1;
    const int qi = qt * QT + ql;

    const float* base = qkv + (size_t)b * BN_T * 3072 + h * 64;

    float qreg[32];
    {
        const float* qp = base + (size_t)qi * 3072 + half * 32;
#pragma unroll
        for (int i = 0; i < 32; i++) qreg[i] = qp[i] * 0.125f;
    }

    float o[32];
#pragma unroll
    for (int i = 0; i < 32; i++) o[i] = 0.f;
    float m = -1e30f, l = 0.f;

    __shared__ float ks[KT][64];
    __shared__ float vs[KT][64];

    const int nkt = qt * 2 + 2;

    for (int kt = 0; kt < nkt; kt++) {
        __syncthreads();
        {
            const int j = tid >> 2;
            const int f = tid & 3;
            const float* kp = base + (size_t)(kt * KT + j) * 3072 + 1024;
            const float* vp = kp + 1024;
#pragma unroll
            for (int it = 0; it < 4; it++) {
                int c = (f + it * 4) * 4;
                *(float4*)&ks[j][c] = *(const float4*)(kp + c);
                *(float4*)&vs[j][c] = *(const float4*)(vp + c);
            }
        }
        __syncthreads();

        float s[KT];
#pragma unroll
        for (int j = 0; j < KT; j++) {
            float p = 0.f;
            const float* kr = &ks[j][half * 32];
#pragma unroll
            for (int i = 0; i < 32; i++) p += qreg[i] * kr[i];
            p += __shfl_xor_sync(0xffffffffu, p, 1);
            int kj = kt * KT + j;
            s[j] = (kj <= qi) ? p : -1e30f;
        }

        float mt = s[0];
#pragma unroll
        for (int j = 1; j < KT; j++) mt = fmaxf(mt, s[j]);
        float mnew = fmaxf(m, mt);
        float corr = __expf(m - mnew);

        float psum = 0.f;
#pragma unroll
        for (int j = 0; j < KT; j++) {
            float e = __expf(s[j] - mnew);
            s[j] = e;
            psum += e;
        }
        l = l * corr + psum;

#pragma unroll
        for (int d = 0; d < 32; d++) {
            float a = o[d] * corr;
#pragma unroll
            for (int j = 0; j < KT; j++)
                a += s[j] * vs[j][half * 32 + d];
            o[d] = a;
        }
        m = mnew;
    }

    const float inv = 1.f / l;
    const int valid = mask[b * BN_T + qi];
    const float qsc = valid ? inv : 0.f;

    float* yp = y + (size_t)(b * BN_T + qi) * DM + h * 64 + half * 32;
#pragma unroll
    for (int dg = 0; dg < 8; dg++) {
        float4 v;
        v.x = o[dg * 4 + 0] * qsc;
        v.y = o[dg * 4 + 1] * qsc;
        v.z = o[dg * 4 + 2] * qsc;
        v.w = o[dg * 4 + 3] * qsc;
        *(float4*)(yp + dg * 4) = v;
    }
}

// ---------------------------------------------------------------------------
extern "C" void kernel_launch(void* const* d_in, const int* in_sizes, int n_in,
                              void* d_out, int out_size)
{
    const float* x    = (const float*)d_in[0];
    const int*   mask = (const int*)  d_in[1];
    const float* Wqkv = (const float*)d_in[2];
    const float* bqkv = (const float*)d_in[3];
    const float* Wo   = (const float*)d_in[4];
    const float* bo   = (const float*)d_in[5];
    float* out = (float*)d_out;

    float *qkv, *yb;
    __nv_bfloat16 *xh, *xl, *wqh, *wql, *woh, *wol, *yh, *yl;
    cudaGetSymbolAddress((void**)&qkv, g_qkv);
    cudaGetSymbolAddress((void**)&yb,  g_y);
    cudaGetSymbolAddress((void**)&xh,  g_xh);
    cudaGetSymbolAddress((void**)&xl,  g_xl);
    cudaGetSymbolAddress((void**)&wqh, g_wqkvh);
    cudaGetSymbolAddress((void**)&wql, g_wqkvl);
    cudaGetSymbolAddress((void**)&woh, g_woh);
    cudaGetSymbolAddress((void**)&wol, g_wol);
    cudaGetSymbolAddress((void**)&yh,  g_yh);
    cudaGetSymbolAddress((void**)&yl,  g_yl);

    cudaFuncSetAttribute(gemm_bf16x3,
                         cudaFuncAttributeMaxDynamicSharedMemorySize, GEMM_SMEM);

    // split inputs to bf16 hi/lo
    split_bf16<<<(MROWS * DM / 4 + 255) / 256, 256>>>(x, xh, xl, MROWS * DM / 4);
    split_bf16<<<(3 * DM * DM / 4 + 255) / 256, 256>>>(Wqkv, wqh, wql, 3 * DM * DM / 4);
    split_bf16<<<(DM * DM / 4 + 255) / 256, 256>>>(Wo, woh, wol, DM * DM / 4);

    // QKV projection: [8192,3072] = x @ Wqkv^T + bqkv
    gemm_bf16x3<<<dim3(3 * DM / 128, MROWS / 128), 256, GEMM_SMEM>>>(
        xh, xl, wqh, wql, bqkv, qkv, 3 * DM, DM);

    // Causal flash attention -> y (invalid query rows zeroed)
    flash_fp32<<<dim3(BN_T / QT, 4 * NH), 128>>>(qkv, mask, yb);

    // split y, then output projection: out = y @ Wo^T + bo
    split_bf16<<<(MROWS * DM / 4 + 255) / 256, 256>>>(yb, yh, yl, MROWS * DM / 4);
    gemm_bf16x3<<<dim3(DM / 128, MROWS / 128), 256, GEMM_SMEM>>>(
        yh, yl, woh, wol, bo, out, DM, DM);
}

// round 5
// speedup vs baseline: 3.8991x; 3.0948x over previous
#include <cuda_runtime.h>
#include <cuda_bf16.h>
#include <cstdint>

#define BN_T 2048
#define DM   1024
#define NH   16
#define HD   64
#define MROWS 8192   // B*T

// ---------------------------------------------------------------------------
// Device-global scratch (allocation-free per harness rules)
// ---------------------------------------------------------------------------
__device__ __align__(16) __nv_bfloat16 g_xh[MROWS * DM];
__device__ __align__(16) __nv_bfloat16 g_xl[MROWS * DM];
__device__ __align__(16) __nv_bfloat16 g_wqkvh[3 * DM * DM];
__device__ __align__(16) __nv_bfloat16 g_wqkvl[3 * DM * DM];
__device__ __align__(16) __nv_bfloat16 g_woh[DM * DM];
__device__ __align__(16) __nv_bfloat16 g_wol[DM * DM];
__device__ __align__(16) __nv_bfloat16 g_qkvh[MROWS * 3 * DM];
__device__ __align__(16) __nv_bfloat16 g_qkvl[MROWS * 3 * DM];
__device__ __align__(16) __nv_bfloat16 g_yh[MROWS * DM];
__device__ __align__(16) __nv_bfloat16 g_yl[MROWS * DM];

// ---------------------------------------------------------------------------
// PTX helpers (baseline PTX only: cp.async + ldmatrix + mma.sync)
// ---------------------------------------------------------------------------
__device__ __forceinline__ uint32_t smem_u32(const void* p) {
    uint32_t a;
    asm("{ .reg .u64 t; cvta.to.shared.u64 t, %1; cvt.u32.u64 %0, t; }"
        : "=r"(a) : "l"(p));
    return a;
}

__device__ __forceinline__ void cp_async16(uint32_t saddr, const void* gaddr) {
    asm volatile("cp.async.cg.shared.global [%0], [%1], 16;"
                 :: "r"(saddr), "l"(gaddr) : "memory");
}
#define CP_COMMIT() asm volatile("cp.async.commit_group;" ::: "memory")
#define CP_WAIT(n)  asm volatile("cp.async.wait_group %0;" :: "n"(n) : "memory")

__device__ __forceinline__ void ldm4(uint32_t* r, uint32_t addr) {
    asm volatile("ldmatrix.sync.aligned.m8n8.x4.shared.b16 {%0,%1,%2,%3}, [%4];"
                 : "=r"(r[0]), "=r"(r[1]), "=r"(r[2]), "=r"(r[3]) : "r"(addr));
}
__device__ __forceinline__ void ldm4t(uint32_t* r, uint32_t addr) {
    asm volatile("ldmatrix.sync.aligned.m8n8.x4.trans.shared.b16 {%0,%1,%2,%3}, [%4];"
                 : "=r"(r[0]), "=r"(r[1]), "=r"(r[2]), "=r"(r[3]) : "r"(addr));
}

__device__ __forceinline__ void mma_bf16(float* d, const uint32_t* a,
                                         uint32_t b0, uint32_t b1) {
    asm volatile(
        "mma.sync.aligned.m16n8k16.row.col.f32.bf16.bf16.f32 "
        "{%0,%1,%2,%3}, {%4,%5,%6,%7}, {%8,%9}, {%0,%1,%2,%3};"
        : "+f"(d[0]), "+f"(d[1]), "+f"(d[2]), "+f"(d[3])
        : "r"(a[0]), "r"(a[1]), "r"(a[2]), "r"(a[3]), "r"(b0), "r"(b1));
}

// ---------------------------------------------------------------------------
// fp32 -> (hi, lo) bf16 split, 4 elems/thread
// ---------------------------------------------------------------------------
__global__ __launch_bounds__(256) void split_bf16(
    const float* __restrict__ in,
    __nv_bfloat16* __restrict__ hi,
    __nv_bfloat16* __restrict__ lo,
    int n4)
{
    int i = blockIdx.x * blockDim.x + threadIdx.x;
    if (i >= n4) return;
    float4 v = ((const float4*)in)[i];
    __nv_bfloat16 h0 = __float2bfloat16(v.x);
    __nv_bfloat16 h1 = __float2bfloat16(v.y);
    __nv_bfloat16 h2 = __float2bfloat16(v.z);
    __nv_bfloat16 h3 = __float2bfloat16(v.w);
    __nv_bfloat16 l0 = __float2bfloat16(v.x - __bfloat162float(h0));
    __nv_bfloat16 l1 = __float2bfloat16(v.y - __bfloat162float(h1));
    __nv_bfloat16 l2 = __float2bfloat16(v.z - __bfloat162float(h2));
    __nv_bfloat16 l3 = __float2bfloat16(v.w - __bfloat162float(h3));
    __nv_bfloat162 hp0(h0, h1), hp1(h2, h3), lp0(l0, l1), lp1(l2, l3);
    ((__nv_bfloat162*)hi)[i * 2]     = hp0;
    ((__nv_bfloat162*)hi)[i * 2 + 1] = hp1;
    ((__nv_bfloat162*)lo)[i * 2]     = lp0;
    ((__nv_bfloat162*)lo)[i * 2 + 1] = lp1;
}

// ---------------------------------------------------------------------------
// C = A @ B^T + bias, split bf16 3-pass HMMA.
// OUTM=0: fp32 C.  OUTM=1: split bf16 (Ch, Cl).
// ---------------------------------------------------------------------------
#define STAGE_BYTES 32768
#define GEMM_SMEM  (3 * STAGE_BYTES)

__device__ __forceinline__ uint32_t sw_off(int row, int c) {
    return (uint32_t)(row * 64 + ((c ^ ((row >> 1) & 3)) * 16));
}

template<int OUTM>
__global__ __launch_bounds__(256, 1) void gemm_bf16x3(
    const __nv_bfloat16* __restrict__ Ah, const __nv_bfloat16* __restrict__ Al,
    const __nv_bfloat16* __restrict__ Bh, const __nv_bfloat16* __restrict__ Bl,
    const float* __restrict__ bias,
    float* __restrict__ C,
    __nv_bfloat16* __restrict__ Ch, __nv_bfloat16* __restrict__ Cl,
    int N, int K)
{
    extern __shared__ char smem[];
    const uint32_t sb = smem_u32(smem);
    const int tid = threadIdx.x;
    const int lane = tid & 31;
    const int wid = tid >> 5;
    const int warpM = wid & 3;
    const int warpN = wid >> 2;
    const int bm = blockIdx.y * 128;
    const int bn = blockIdx.x * 128;
    const int NC = K >> 5;

    const int g  = lane >> 3;
    const int l7 = lane & 7;
    const int arow = (g & 1) * 8 + l7;
    const int acg  = g >> 1;
    const int brow = (g >> 1) * 8 + l7;
    const int bcg  = g & 1;

    uint32_t aRow[2], aSw[2];
#pragma unroll
    for (int mt = 0; mt < 2; mt++) {
        int r = warpM * 32 + mt * 16 + arow;
        aRow[mt] = (uint32_t)(r * 64);
        aSw[mt] = (uint32_t)((r >> 1) & 3);
    }
    uint32_t bRow[4], bSw[4];
#pragma unroll
    for (int ng = 0; ng < 4; ng++) {
        int r = warpN * 64 + ng * 16 + brow;
        bRow[ng] = (uint32_t)(r * 64);
        bSw[ng] = (uint32_t)((r >> 1) & 3);
    }

    float acc[2][8][4];
#pragma unroll
    for (int mt = 0; mt < 2; mt++)
#pragma unroll
        for (int nt = 0; nt < 8; nt++)
#pragma unroll
            for (int e = 0; e < 4; e++) acc[mt][nt][e] = 0.f;

    const __nv_bfloat16* srcA[2] = { Ah + (size_t)bm * K, Al + (size_t)bm * K };
    const __nv_bfloat16* srcB[2] = { Bh + (size_t)bn * K, Bl + (size_t)bn * K };

    auto load_stage = [&](int kc, int st) {
        const uint32_t stbase = sb + st * STAGE_BYTES;
#pragma unroll
        for (int q = 0; q < 8; q++) {
            int cid = tid + q * 256;
            int sub = cid >> 9;
            int ci  = cid & 511;
            int row = ci >> 2;
            int c   = ci & 3;
            uint32_t saddr = stbase + sub * 8192 + sw_off(row, c);
            const __nv_bfloat16* gp =
                (sub < 2 ? srcA[sub] : srcB[sub - 2])
                + (size_t)row * K + kc * 32 + c * 8;
            cp_async16(saddr, gp);
        }
        CP_COMMIT();
    };

    load_stage(0, 0);
    load_stage(1, 1);

    for (int i = 0; i < NC; i++) {
        if (i < NC - 1) { CP_WAIT(1); } else { CP_WAIT(0); }
        __syncthreads();

        const uint32_t stbase = sb + (i % 3) * STAGE_BYTES;
#pragma unroll
        for (int ks = 0; ks < 2; ks++) {
            uint32_t ah[2][4], al[2][4];
#pragma unroll
            for (int mt = 0; mt < 2; mt++) {
                uint32_t slot = (uint32_t)((2 * ks + acg) ^ aSw[mt]) * 16;
                ldm4(ah[mt], stbase + 0    + aRow[mt] + slot);
                ldm4(al[mt], stbase + 8192 + aRow[mt] + slot);
            }
            uint32_t bh[4][4], bl[4][4];
#pragma unroll
            for (int ng = 0; ng < 4; ng++) {
                uint32_t slot = (uint32_t)((2 * ks + bcg) ^ bSw[ng]) * 16;
                ldm4(bh[ng], stbase + 16384 + bRow[ng] + slot);
                ldm4(bl[ng], stbase + 24576 + bRow[ng] + slot);
            }
#pragma unroll
            for (int mt = 0; mt < 2; mt++) {
#pragma unroll
                for (int ng = 0; ng < 4; ng++) {
                    mma_bf16(acc[mt][2 * ng],     ah[mt], bh[ng][0], bh[ng][1]);
                    mma_bf16(acc[mt][2 * ng],     ah[mt], bl[ng][0], bl[ng][1]);
                    mma_bf16(acc[mt][2 * ng],     al[mt], bh[ng][0], bh[ng][1]);
                    mma_bf16(acc[mt][2 * ng + 1], ah[mt], bh[ng][2], bh[ng][3]);
                    mma_bf16(acc[mt][2 * ng + 1], ah[mt], bl[ng][2], bl[ng][3]);
                    mma_bf16(acc[mt][2 * ng + 1], al[mt], bh[ng][2], bh[ng][3]);
                }
            }
        }

        __syncthreads();
        if (i + 2 < NC) load_stage(i + 2, (i + 2) % 3);
    }

#pragma unroll
    for (int mt = 0; mt < 2; mt++) {
#pragma unroll
        for (int nt = 0; nt < 8; nt++) {
            int row0 = bm + warpM * 32 + mt * 16 + (lane >> 2);
            int col  = bn + warpN * 64 + nt * 8 + (lane & 3) * 2;
            float b0 = bias[col], b1 = bias[col + 1];
            float v0 = acc[mt][nt][0] + b0, v1 = acc[mt][nt][1] + b1;
            float v2 = acc[mt][nt][2] + b0, v3 = acc[mt][nt][3] + b1;
            if (OUTM == 0) {
                float2 p0 = { v0, v1 }, p1 = { v2, v3 };
                *(float2*)(C + (size_t)row0 * N + col) = p0;
                *(float2*)(C + (size_t)(row0 + 8) * N + col) = p1;
            } else {
                __nv_bfloat16 h0 = __float2bfloat16(v0), h1 = __float2bfloat16(v1);
                __nv_bfloat16 h2 = __float2bfloat16(v2), h3 = __float2bfloat16(v3);
                __nv_bfloat162 hp0(h0, h1), hp1(h2, h3);
                __nv_bfloat162 lp0(__float2bfloat16(v0 - __bfloat162float(h0)),
                                   __float2bfloat16(v1 - __bfloat162float(h1)));
                __nv_bfloat162 lp1(__float2bfloat16(v2 - __bfloat162float(h2)),
                                   __float2bfloat16(v3 - __bfloat162float(h3)));
                *(uint32_t*)(Ch + (size_t)row0 * N + col) = *(uint32_t*)&hp0;
                *(uint32_t*)(Cl + (size_t)row0 * N + col) = *(uint32_t*)&lp0;
                *(uint32_t*)(Ch + (size_t)(row0 + 8) * N + col) = *(uint32_t*)&hp1;
                *(uint32_t*)(Cl + (size_t)(row0 + 8) * N + col) = *(uint32_t*)&lp1;
            }
        }
    }
}

// ---------------------------------------------------------------------------
// Causal flash attention, bf16x3 HMMA.
// grid (16, B*NH); CTA: 128-query tile for one (b,h); 256 threads / 8 warps.
// K/V tiles of 64 keys, double-buffered cp.async. Writes yh/yl bf16 split,
// invalid query rows zeroed.
// ---------------------------------------------------------------------------
#define FSMEM (32768 + 2 * 32768)   // Qh|Ql (32K) + 2 stages of Kh|Kl|Vh|Vl

__global__ __launch_bounds__(256, 1) void flash_hmma(
    const __nv_bfloat16* __restrict__ qkvh,
    const __nv_bfloat16* __restrict__ qkvl,
    const int* __restrict__ mask,
    __nv_bfloat16* __restrict__ yh,
    __nv_bfloat16* __restrict__ yl)
{
    extern __shared__ char smem[];
    const uint32_t sb = smem_u32(smem);
    const int tid = threadIdx.x;
    const int lane = tid & 31, wid = tid >> 5;
    const int qt = 15 - (int)blockIdx.x;          // descending work order
    const int bh = blockIdx.y, b = bh >> 4, h = bh & 15;
    const int nkt = 2 * qt + 2;
    const int l7 = lane & 7, bit3 = (lane >> 3) & 1, bit4 = (lane >> 4) & 1;

    const uint32_t QH = sb, QL = sb + 16384, ST = sb + 32768;

    // Q load (group 0): 128 rows x 128B x {h,l}
    {
        const size_t rq = (size_t)(b * BN_T + qt * 128);
#pragma unroll
        for (int q = 0; q < 8; q++) {
            int cid = q * 256 + tid;
            int arr = cid >> 10, ci = cid & 1023, row = ci >> 3, c = ci & 7;
            const __nv_bfloat16* gp = (arr ? qkvl : qkvh)
                + (rq + row) * 3072 + h * 64 + c * 8;
            cp_async16(sb + arr * 16384 + row * 128 + (((c ^ (row & 7))) << 4), gp);
        }
        CP_COMMIT();
    }

    auto load_kv = [&](int kt, int st) {
        const uint32_t base = ST + st * 32768;
        const size_t rk = (size_t)(b * BN_T + kt * 64);
#pragma unroll
        for (int q = 0; q < 8; q++) {
            int cid = q * 256 + tid;
            int sub = cid >> 9, ci = cid & 511, row = ci >> 3, c = ci & 7;
            const __nv_bfloat16* src = (sub & 1) ? qkvl : qkvh;
            int colb = (sub >> 1) ? (2048 + h * 64) : (1024 + h * 64);
            const __nv_bfloat16* gp = src + (rk + row) * 3072 + colb + c * 8;
            cp_async16(base + sub * 8192 + row * 128 + (((c ^ (row & 7))) << 4), gp);
        }
        CP_COMMIT();
    };

    load_kv(0, 0);
    load_kv(1, 1);

    CP_WAIT(2);            // Q resident
    __syncthreads();

    // Q fragments (register-resident)
    uint32_t qhf[4][4], qlf[4][4];
    {
        const uint32_t rb = (uint32_t)((wid * 16 + bit3 * 8 + l7) * 128);
#pragma unroll
        for (int ks = 0; ks < 4; ks++) {
            uint32_t sl = ((uint32_t)((ks * 2 + bit4) ^ l7)) << 4;
            ldm4(qhf[ks], QH + rb + sl);
            ldm4(qlf[ks], QL + rb + sl);
        }
    }

    float o[8][4];
#pragma unroll
    for (int nt = 0; nt < 8; nt++)
#pragma unroll
        for (int e = 0; e < 4; e++) o[nt][e] = 0.f;
    float m0 = -1e30f, m1 = -1e30f, l0 = 0.f, l1 = 0.f;

    const int row0 = qt * 128 + wid * 16 + (lane >> 2);
    const int col_in = (lane & 3) * 2;

    for (int kt = 0; kt < nkt; kt++) {
        if (kt + 1 < nkt) { CP_WAIT(1); } else { CP_WAIT(0); }
        __syncthreads();
        const uint32_t kb = ST + (kt & 1) * 32768;

        // ---- S = (Q Kᵀ) * 0.125, 3-pass ----
        float s[8][4];
#pragma unroll
        for (int nt = 0; nt < 8; nt++)
#pragma unroll
            for (int e = 0; e < 4; e++) s[nt][e] = 0.f;

#pragma unroll
        for (int ks = 0; ks < 4; ks++) {
            uint32_t kh4[4][4], kl4[4][4];
#pragma unroll
            for (int np = 0; np < 4; np++) {
                uint32_t rb = (uint32_t)((np * 16 + bit4 * 8 + l7) * 128);
                uint32_t sl = ((uint32_t)((ks * 2 + bit3) ^ l7)) << 4;
                ldm4(kh4[np], kb + rb + sl);
                ldm4(kl4[np], kb + 8192 + rb + sl);
            }
#pragma unroll
            for (int np = 0; np < 4; np++) {
                mma_bf16(s[2*np],   qhf[ks], kh4[np][0], kh4[np][1]);
                mma_bf16(s[2*np],   qhf[ks], kl4[np][0], kl4[np][1]);
                mma_bf16(s[2*np],   qlf[ks], kh4[np][0], kh4[np][1]);
                mma_bf16(s[2*np+1], qhf[ks], kh4[np][2], kh4[np][3]);
                mma_bf16(s[2*np+1], qhf[ks], kl4[np][2], kl4[np][3]);
                mma_bf16(s[2*np+1], qlf[ks], kh4[np][2], kh4[np][3]);
            }
        }

        const bool diag = (kt >= 2 * qt);
#pragma unroll
        for (int nt = 0; nt < 8; nt++) {
#pragma unroll
            for (int e = 0; e < 4; e++) s[nt][e] *= 0.125f;
            if (diag) {
                int key = kt * 64 + nt * 8 + col_in;
                if (key     > row0)     s[nt][0] = -1e30f;
                if (key + 1 > row0)     s[nt][1] = -1e30f;
                if (key     > row0 + 8) s[nt][2] = -1e30f;
                if (key + 1 > row0 + 8) s[nt][3] = -1e30f;
            }
        }

        // ---- online softmax ----
        float rm0 = s[0][0], rm1 = s[0][2];
#pragma unroll
        for (int nt = 0; nt < 8; nt++) {
            rm0 = fmaxf(rm0, fmaxf(s[nt][0], s[nt][1]));
            rm1 = fmaxf(rm1, fmaxf(s[nt][2], s[nt][3]));
        }
        rm0 = fmaxf(rm0, __shfl_xor_sync(~0u, rm0, 1));
        rm0 = fmaxf(rm0, __shfl_xor_sync(~0u, rm0, 2));
        rm1 = fmaxf(rm1, __shfl_xor_sync(~0u, rm1, 1));
        rm1 = fmaxf(rm1, __shfl_xor_sync(~0u, rm1, 2));
        float mn0 = fmaxf(m0, rm0), mn1 = fmaxf(m1, rm1);
        float c0 = __expf(m0 - mn0), c1 = __expf(m1 - mn1);
        float sum0 = 0.f, sum1 = 0.f;
#pragma unroll
        for (int nt = 0; nt < 8; nt++) {
            s[nt][0] = __expf(s[nt][0] - mn0);
            s[nt][1] = __expf(s[nt][1] - mn0);
            s[nt][2] = __expf(s[nt][2] - mn1);
            s[nt][3] = __expf(s[nt][3] - mn1);
            sum0 += s[nt][0] + s[nt][1];
            sum1 += s[nt][2] + s[nt][3];
        }
        sum0 += __shfl_xor_sync(~0u, sum0, 1);
        sum0 += __shfl_xor_sync(~0u, sum0, 2);
        sum1 += __shfl_xor_sync(~0u, sum1, 1);
        sum1 += __shfl_xor_sync(~0u, sum1, 2);
        l0 = l0 * c0 + sum0; l1 = l1 * c1 + sum1;
        m0 = mn0; m1 = mn1;
#pragma unroll
        for (int nt = 0; nt < 8; nt++) {
            o[nt][0] *= c0; o[nt][1] *= c0;
            o[nt][2] *= c1; o[nt][3] *= c1;
        }

        // ---- pack P into hi/lo A-fragments ----
        uint32_t pah[4][4], pal[4][4];
#pragma unroll
        for (int j = 0; j < 4; j++) {
#pragma unroll
            for (int e = 0; e < 4; e++) {
                int nt = 2 * j + (e >> 1);
                int li = (e & 1) * 2;
                float v0 = s[nt][li], v1 = s[nt][li + 1];
                __nv_bfloat16 h0 = __float2bfloat16(v0);
                __nv_bfloat16 h1 = __float2bfloat16(v1);
                __nv_bfloat162 hp(h0, h1);
                __nv_bfloat162 lp(__float2bfloat16(v0 - __bfloat162float(h0)),
                                  __float2bfloat16(v1 - __bfloat162float(h1)));
                pah[j][e] = *(uint32_t*)&hp;
                pal[j][e] = *(uint32_t*)&lp;
            }
        }

        // ---- O += P V, 3-pass (V via ldmatrix.trans) ----
#pragma unroll
        for (int j = 0; j < 4; j++) {
            uint32_t vh4[4][4], vl4[4][4];
#pragma unroll
            for (int g = 0; g < 4; g++) {
                uint32_t rb = (uint32_t)((j * 16 + bit3 * 8 + l7) * 128);
                uint32_t sl = ((uint32_t)((g * 2 + bit4) ^ l7)) << 4;
                ldm4t(vh4[g], kb + 16384 + rb + sl);
                ldm4t(vl4[g], kb + 24576 + rb + sl);
            }
#pragma unroll
            for (int g = 0; g < 4; g++) {
                mma_bf16(o[2*g],   pah[j], vh4[g][0], vh4[g][1]);
                mma_bf16(o[2*g],   pah[j], vl4[g][0], vl4[g][1]);
                mma_bf16(o[2*g],   pal[j], vh4[g][0], vh4[g][1]);
                mma_bf16(o[2*g+1], pah[j], vh4[g][2], vh4[g][3]);
                mma_bf16(o[2*g+1], pah[j], vl4[g][2], vl4[g][3]);
                mma_bf16(o[2*g+1], pal[j], vh4[g][2], vh4[g][3]);
            }
        }

        __syncthreads();
        if (kt + 2 < nkt) load_kv(kt + 2, kt & 1);
    }

    // ---- epilogue: normalize, query-mask, split-write y ----
    const int gr0 = b * BN_T + row0;
    const float sc0 = (mask[gr0] ? 1.f : 0.f) / l0;
    const float sc1 = (mask[gr0 + 8] ? 1.f : 0.f) / l1;
#pragma unroll
    for (int nt = 0; nt < 8; nt++) {
        int col = h * 64 + nt * 8 + col_in;
        float v0 = o[nt][0] * sc0, v1 = o[nt][1] * sc0;
        float v2 = o[nt][2] * sc1, v3 = o[nt][3] * sc1;
        __nv_bfloat16 h0 = __float2bfloat16(v0), h1 = __float2bfloat16(v1);
        __nv_bfloat16 h2 = __float2bfloat16(v2), h3 = __float2bfloat16(v3);
        __nv_bfloat162 hp0(h0, h1), hp1(h2, h3);
        __nv_bfloat162 lp0(__float2bfloat16(v0 - __bfloat162float(h0)),
                           __float2bfloat16(v1 - __bfloat162float(h1)));
        __nv_bfloat162 lp1(__float2bfloat16(v2 - __bfloat162float(h2)),
                           __float2bfloat16(v3 - __bfloat162float(h3)));
        *(uint32_t*)(yh + (size_t)gr0 * DM + col) = *(uint32_t*)&hp0;
        *(uint32_t*)(yl + (size_t)gr0 * DM + col) = *(uint32_t*)&lp0;
        *(uint32_t*)(yh + (size_t)(gr0 + 8) * DM + col) = *(uint32_t*)&hp1;
        *(uint32_t*)(yl + (size_t)(gr0 + 8) * DM + col) = *(uint32_t*)&lp1;
    }
}

// ---------------------------------------------------------------------------
extern "C" void kernel_launch(void* const* d_in, const int* in_sizes, int n_in,
                              void* d_out, int out_size)
{
    const float* x    = (const float*)d_in[0];
    const int*   mask = (const int*)  d_in[1];
    const float* Wqkv = (const float*)d_in[2];
    const float* bqkv = (const float*)d_in[3];
    const float* Wo   = (const float*)d_in[4];
    const float* bo   = (const float*)d_in[5];
    float* out = (float*)d_out;

    __nv_bfloat16 *xh, *xl, *wqh, *wql, *woh, *wol, *qh, *ql, *yh, *yl;
    cudaGetSymbolAddress((void**)&xh,  g_xh);
    cudaGetSymbolAddress((void**)&xl,  g_xl);
    cudaGetSymbolAddress((void**)&wqh, g_wqkvh);
    cudaGetSymbolAddress((void**)&wql, g_wqkvl);
    cudaGetSymbolAddress((void**)&woh, g_woh);
    cudaGetSymbolAddress((void**)&wol, g_wol);
    cudaGetSymbolAddress((void**)&qh,  g_qkvh);
    cudaGetSymbolAddress((void**)&ql,  g_qkvl);
    cudaGetSymbolAddress((void**)&yh,  g_yh);
    cudaGetSymbolAddress((void**)&yl,  g_yl);

    cudaFuncSetAttribute(gemm_bf16x3<0>,
                         cudaFuncAttributeMaxDynamicSharedMemorySize, GEMM_SMEM);
    cudaFuncSetAttribute(gemm_bf16x3<1>,
                         cudaFuncAttributeMaxDynamicSharedMemorySize, GEMM_SMEM);
    cudaFuncSetAttribute(flash_hmma,
                         cudaFuncAttributeMaxDynamicSharedMemorySize, FSMEM);

    split_bf16<<<(MROWS * DM / 4 + 255) / 256, 256>>>(x, xh, xl, MROWS * DM / 4);
    split_bf16<<<(3 * DM * DM / 4 + 255) / 256, 256>>>(Wqkv, wqh, wql, 3 * DM * DM / 4);
    split_bf16<<<(DM * DM / 4 + 255) / 256, 256>>>(Wo, woh, wol, DM * DM / 4);

    // QKV projection -> split bf16 qkv
    gemm_bf16x3<1><<<dim3(3 * DM / 128, MROWS / 128), 256, GEMM_SMEM>>>(
        xh, xl, wqh, wql, bqkv, nullptr, qh, ql, 3 * DM, DM);

    // Causal flash attention (HMMA) -> split bf16 y
    flash_hmma<<<dim3(16, 4 * NH), 256, FSMEM>>>(qh, ql, mask, yh, yl);

    // Output projection -> fp32 out
    gemm_bf16x3<0><<<dim3(DM / 128, MROWS / 128), 256, GEMM_SMEM>>>(
        yh, yl, woh, wol, bo, out, nullptr, nullptr, DM, DM);
}